// round 8
// baseline (speedup 1.0000x reference)
#include <cuda_runtime.h>
#include <cuda_bf16.h>
#include <cstdint>

#define NB 64
#define CC 32
#define KK 5
#define ADIM 4
#define AHID 256

// packed f32x2 helpers
#define PACK2(out, lo, hi) \
    asm("mov.b64 %0, {%1, %2};" : "=l"(out) : "r"(lo), "r"(hi))
#define FMA2(acc, a, b) \
    asm("fma.rn.f32x2 %0, %1, %2, %0;" : "+l"(acc) : "l"(a), "l"(b))
#define UNPACK2(lo, hi, in) \
    asm("mov.b64 {%0, %1}, %2;" : "=r"(lo), "=r"(hi) : "l"(in))

__device__ __forceinline__ unsigned long long pack_dup(float v) {
    unsigned long long r; unsigned u = __float_as_uint(v);
    PACK2(r, u, u); return r;
}

// mma.sync m16n8k16 bf16
#define MMA16816(d, a0, a1, a2, a3, b0, b1) \
    asm volatile("mma.sync.aligned.m16n8k16.row.col.f32.bf16.bf16.f32 " \
        "{%0,%1,%2,%3}, {%4,%5,%6,%7}, {%8,%9}, {%0,%1,%2,%3};" \
        : "+f"((d)[0]), "+f"((d)[1]), "+f"((d)[2]), "+f"((d)[3]) \
        : "r"(a0), "r"(a1), "r"(a2), "r"(a3), "r"(b0), "r"(b1))

// ---------------- scratch ----------------
__device__ uint32_t g_h1hi[NB * 16 * 128 * 128];
__device__ uint32_t g_h1lo[NB * 16 * 128 * 128];
__device__ float g_h2[NB * CC * 64 * 64];
__device__ float g_ker[NB * CC * KK * KK];
__device__ float g_sa[NB * CC * 64 * 64];
__device__ float g_f [NB * CC * 64 * 64];
__device__ uint32_t g_wtu[25 * 1024];

// =================== action encoder MLP ===================
__global__ void ae_kernel(const float* __restrict__ act,
                          const float* __restrict__ w1, const float* __restrict__ b1,
                          const float* __restrict__ w2, const float* __restrict__ b2) {
    __shared__ float sH[AHID];
    __shared__ float sA[ADIM];
    int n = blockIdx.x, tid = threadIdx.x;
    if (tid < ADIM) sA[tid] = act[n * ADIM + tid];
    __syncthreads();
    float h = b1[tid];
#pragma unroll
    for (int i = 0; i < ADIM; i++) h = fmaf(sA[i], w1[i * AHID + tid], h);
    sH[tid] = fmaxf(h, 0.f);
    __syncthreads();
    for (int o = tid; o < CC * KK * KK; o += 256) {
        float acc = b2[o];
#pragma unroll 8
        for (int j = 0; j < AHID; j++) acc = fmaf(sH[j], w2[j * (CC * KK * KK) + o], acc);
        g_ker[n * (CC * KK * KK) + o] = acc;
    }
}

// =================== conv2 weight pre-split ===================
__global__ void wsplit_kernel(const float* __restrict__ w) {
    int i = blockIdx.x * 256 + threadIdx.x;
    if (i >= 25 * 512) return;
    int tap = i >> 9, rr = i & 511, oc = rr >> 4, p = rr & 15;
    float f0 = w[(oc * 32 + 2 * p) * 25 + tap];
    float f1 = w[(oc * 32 + 2 * p + 1) * 25 + tap];
    __nv_bfloat162 hp, lp;
    hp.x = __float2bfloat16(f0); hp.y = __float2bfloat16(f1);
    lp.x = __float2bfloat16(f0 - __bfloat162float(hp.x));
    lp.y = __float2bfloat16(f1 - __bfloat162float(hp.y));
    g_wtu[tap * 1024 + oc * 16 + p] = *(uint32_t*)&hp;
    g_wtu[tap * 1024 + 512 + oc * 16 + p] = *(uint32_t*)&lp;
}

// =================== conv1: 3->32, k5, s2, p2, NHWC in ===================
__global__ void __launch_bounds__(256, 2)
conv1_kernel(const float* __restrict__ img,
             const float* __restrict__ w, const float* __restrict__ b) {
    __shared__ __align__(16) float sIn[2][3 * 35 * 34];
    __shared__ __align__(16) float sW[75 * 32];
    __shared__ __align__(8) float sB[32];
    int n = blockIdx.z;
    int ox0 = blockIdx.x * 32, oy0 = blockIdx.y * 16;
    int tid = threadIdx.x;

    for (int i = tid; i < 75 * 32; i += 256) {
        int o = i & 31, tap = i >> 5;
        int c = tap / 25, r = tap % 25, kh = r / 5, kw = r % 5;
        sW[i] = w[((o * 3 + c) * 5 + kh) * 5 + kw];
    }
    if (tid < 32) sB[tid] = b[tid];

    int iy0 = oy0 * 2 - 2, ix0 = ox0 * 2 - 2;
    for (int i = tid; i < 3 * 35 * 67; i += 256) {
        int c = i / (35 * 67), r = i % (35 * 67);
        int iy = r / 67, ix = r % 67;
        int gy = iy0 + iy, gx = ix0 + ix;
        float v = 0.f;
        if ((unsigned)gy < 256u && (unsigned)gx < 256u)
            v = img[((n * 256 + gy) * 256 + gx) * 3 + c];
        sIn[ix & 1][c * 1190 + iy * 34 + (ix >> 1)] = v;
    }
    __syncthreads();

    int ox = tid & 31, oyr = tid >> 5;
    unsigned long long accA[16], accB[16];
    const unsigned long long* sB2 = (const unsigned long long*)sB;
#pragma unroll
    for (int o = 0; o < 16; o++) { accA[o] = sB2[o]; accB[o] = sB2[o]; }

    for (int c = 0; c < 3; c++)
        for (int kh = 0; kh < 5; kh++) {
            int base = c * 1190 + (2 * oyr + kh) * 34 + ox;
            const float* pl[2] = { &sIn[0][base], &sIn[1][base] };
#pragma unroll
            for (int kw = 0; kw < 5; kw++) {
                float fA = pl[kw & 1][kw >> 1];
                float fB = pl[kw & 1][(kw >> 1) + 544];
                unsigned long long vA2 = pack_dup(fA);
                unsigned long long vB2 = pack_dup(fB);
                const ulonglong2* wq =
                    (const ulonglong2*)&sW[((c * 5 + kh) * 5 + kw) * 32];
#pragma unroll
                for (int o2 = 0; o2 < 8; o2++) {
                    ulonglong2 ww = wq[o2];
                    FMA2(accA[2 * o2], vA2, ww.x);
                    FMA2(accA[2 * o2 + 1], vA2, ww.y);
                    FMA2(accB[2 * o2], vB2, ww.x);
                    FMA2(accB[2 * o2 + 1], vB2, ww.y);
                }
            }
        }

    int gyA = oy0 + oyr, gyB = gyA + 8, gx = ox0 + ox;
#pragma unroll
    for (int o = 0; o < 16; o++) {
        unsigned lo_, hi_;
        UNPACK2(lo_, hi_, accA[o]);
        float f0 = fmaxf(__uint_as_float(lo_), 0.f);
        float f1 = fmaxf(__uint_as_float(hi_), 0.f);
        __nv_bfloat162 hp, lp;
        hp.x = __float2bfloat16(f0); hp.y = __float2bfloat16(f1);
        lp.x = __float2bfloat16(f0 - __bfloat162float(hp.x));
        lp.y = __float2bfloat16(f1 - __bfloat162float(hp.y));
        g_h1hi[((n * 16 + o) * 128 + gyA) * 128 + gx] = *(uint32_t*)&hp;
        g_h1lo[((n * 16 + o) * 128 + gyA) * 128 + gx] = *(uint32_t*)&lp;
        UNPACK2(lo_, hi_, accB[o]);
        f0 = fmaxf(__uint_as_float(lo_), 0.f);
        f1 = fmaxf(__uint_as_float(hi_), 0.f);
        hp.x = __float2bfloat16(f0); hp.y = __float2bfloat16(f1);
        lp.x = __float2bfloat16(f0 - __bfloat162float(hp.x));
        lp.y = __float2bfloat16(f1 - __bfloat162float(hp.y));
        g_h1hi[((n * 16 + o) * 128 + gyB) * 128 + gx] = *(uint32_t*)&hp;
        g_h1lo[((n * 16 + o) * 128 + gyB) * 128 + gx] = *(uint32_t*)&lp;
    }
}

// =================== conv2 via mma.sync: barrier-free mainloop ===================
// M=128 px/block (2 output rows). ALL 25 taps of weights resident in smem.
// smem u32 map: [0..26400) weights [tap][{hi 528, lo 528}] (p*33+oc pad layout)
//               [26400..41296) halo HI [16p][7y][133x]
//               [41296..56192) halo LO
#define C2_PLANE 931           // 7*133
#define C2_HIOFF 26400
#define C2_LOOFF 41296
#define C2_SMEM  (56192 * 4)   // 224768 B

__global__ void __launch_bounds__(256, 1)
conv2_mma_kernel(const uint32_t* __restrict__ h1hi, const uint32_t* __restrict__ h1lo,
                 const uint32_t* __restrict__ wsp, const float* __restrict__ bias,
                 float* __restrict__ h2) {
    extern __shared__ __align__(16) uint32_t sm[];
    uint32_t* sW = sm;
    uint32_t* sHI = sm + C2_HIOFF;
    uint32_t* sLO = sm + C2_LOOFF;
    int tid = threadIdx.x;
    int ytile = blockIdx.x, n = blockIdx.y;   // 2 output rows per block

    // ---- all 25 taps of weights -> smem ([p][33-pad oc]) ----
    for (int j = tid; j < 25600; j += 256) {
        int tap = j >> 10, rr = j & 1023;
        int term = rr >> 9, r2 = rr & 511, oc = r2 >> 4, p = r2 & 15;
        sW[tap * 1056 + term * 528 + p * 33 + oc] = wsp[j];
    }
    // ---- halo (7 rows) ----
    int gy0 = 4 * ytile - 2;
    const uint32_t* hib = h1hi + (size_t)n * 16 * 16384;
    const uint32_t* lob = h1lo + (size_t)n * 16 * 16384;
    for (int i = tid; i < 16 * 7 * 132; i += 256) {
        int py = i / 132, x = i % 132;
        int p = py / 7, y = py % 7;
        int gy = gy0 + y, gx = x - 2;
        uint32_t vh = 0, vl = 0;
        if ((unsigned)gy < 128u && (unsigned)gx < 128u) {
            int off = p * 16384 + gy * 128 + gx;
            vh = hib[off]; vl = lob[off];
        }
        int sa = p * C2_PLANE + y * 133 + x;
        sHI[sa] = vh; sLO[sa] = vl;
    }
    __syncthreads();
    // ============ barrier-free mainloop ============

    int lane = tid & 31, w = tid >> 5;
    int r = lane >> 2, q = lane & 3;
    int pxb = w * 16;                    // warp's 16-px m-tile
    int yrow = pxb >> 6;                 // output row within block (0/1)
    int xoff = (pxb & 63) + r;           // x of a0 row

    float acc[4][4];
#pragma unroll
    for (int nt = 0; nt < 4; nt++)
#pragma unroll
        for (int e = 0; e < 4; e++) acc[nt][e] = 0.f;

    for (int kh = 0; kh < 5; kh++) {
#pragma unroll
        for (int kw = 0; kw < 5; kw++) {
            const uint32_t* bw = &sW[(kh * 5 + kw) * 1056];
            int y = 2 * yrow + kh;
            int xb = 2 * xoff + kw;
#pragma unroll
            for (int ks = 0; ks < 2; ks++) {
                int p0 = q + 8 * ks, p2 = q + 4 + 8 * ks;
                int b0 = p0 * C2_PLANE + y * 133 + xb;
                int b2 = p2 * C2_PLANE + y * 133 + xb;
                uint32_t AH0 = sHI[b0], AH1 = sHI[b0 + 16];
                uint32_t AH2 = sHI[b2], AH3 = sHI[b2 + 16];
                uint32_t AL0 = sLO[b0], AL1 = sLO[b0 + 16];
                uint32_t AL2 = sLO[b2], AL3 = sLO[b2 + 16];
                uint32_t BH[4][2], BL[4][2];
#pragma unroll
                for (int nt = 0; nt < 4; nt++) {
                    int oc = nt * 8 + r;
                    BH[nt][0] = bw[p0 * 33 + oc];
                    BH[nt][1] = bw[p2 * 33 + oc];
                    BL[nt][0] = bw[528 + p0 * 33 + oc];
                    BL[nt][1] = bw[528 + p2 * 33 + oc];
                }
#pragma unroll
                for (int nt = 0; nt < 4; nt++)
                    MMA16816(acc[nt], AH0, AH1, AH2, AH3, BH[nt][0], BH[nt][1]);
#pragma unroll
                for (int nt = 0; nt < 4; nt++)
                    MMA16816(acc[nt], AL0, AL1, AL2, AL3, BH[nt][0], BH[nt][1]);
#pragma unroll
                for (int nt = 0; nt < 4; nt++)
                    MMA16816(acc[nt], AH0, AH1, AH2, AH3, BL[nt][0], BL[nt][1]);
            }
        }
    }

    // ---- epilogue: stage through smem, coalesced bias+relu store ----
    __syncthreads();
    float* sD = (float*)sm;      // 32 oc x 128 px
    int px = pxb + r;
#pragma unroll
    for (int nt = 0; nt < 4; nt++) {
        int oc = nt * 8 + 2 * q;
        sD[oc * 128 + px] = acc[nt][0];
        sD[(oc + 1) * 128 + px] = acc[nt][1];
        sD[oc * 128 + px + 8] = acc[nt][2];
        sD[(oc + 1) * 128 + px + 8] = acc[nt][3];
    }
    __syncthreads();
    float* outb = h2 + (size_t)n * 32 * 4096;
    for (int j = tid; j < 4096; j += 256) {
        int oc = j >> 7, m = j & 127;
        int gy = 2 * ytile + (m >> 6), gx = m & 63;
        outb[oc * 4096 + gy * 64 + gx] = fmaxf(sD[j] + __ldg(&bias[oc]), 0.f);
    }
}

// =================== cross-conv: depthwise k5 p2, register row-reuse ===================
__global__ void __launch_bounds__(256)
xconv_kernel() {
    __shared__ float sIn[68 * 68];
    __shared__ float sK[25];
    int c = blockIdx.x, n = blockIdx.y;
    int tid = threadIdx.x;
    const float* src = &g_h2[(n * 32 + c) * 4096];
    for (int i = tid; i < 68 * 68; i += 256) {
        int iy = i / 68, ix = i % 68;
        int gy = iy - 2, gx = ix - 2;
        sIn[i] = ((unsigned)gy < 64u && (unsigned)gx < 64u) ? src[gy * 64 + gx] : 0.f;
    }
    if (tid < 25) sK[tid] = g_ker[(n * 32 + c) * 25 + tid];
    __syncthreads();
    float k[25];
#pragma unroll
    for (int t = 0; t < 25; t++) k[t] = sK[t];

    int tx = tid & 63, ty = tid >> 6;
    int ybase = ty * 16;
    float acc[16];
#pragma unroll
    for (int j = 0; j < 16; j++) acc[j] = 0.f;

#pragma unroll
    for (int iy = 0; iy < 20; iy++) {
        const float* row = &sIn[(ybase + iy) * 68 + tx];
        float v0 = row[0], v1 = row[1], v2 = row[2], v3 = row[3], v4 = row[4];
#pragma unroll
        for (int kh = 0; kh < 5; kh++) {
            int j = iy - kh;
            if (j >= 0 && j < 16) {
                float a = acc[j];
                a = fmaf(v0, k[kh * 5 + 0], a);
                a = fmaf(v1, k[kh * 5 + 1], a);
                a = fmaf(v2, k[kh * 5 + 2], a);
                a = fmaf(v3, k[kh * 5 + 3], a);
                a = fmaf(v4, k[kh * 5 + 4], a);
                acc[j] = a;
            }
        }
    }
    float* dst = &g_sa[(n * 32 + c) * 4096 + tx];
#pragma unroll
    for (int j = 0; j < 16; j++) dst[(ybase + j) * 64] = acc[j];
}

// =================== mp1: 32->32, k3, p1, relu (scalar FFMA2) ===================
__global__ void __launch_bounds__(256, 2)
mp1_kernel(const float* __restrict__ w, const float* __restrict__ b) {
    __shared__ __align__(16) float sIn[2][18 * 34];
    __shared__ __align__(16) float sW[2][288];
    __shared__ __align__(8) float sB[32];
    int n = blockIdx.z;
    int ox0 = blockIdx.x * 32, oy0 = blockIdx.y * 16;
    int tid = threadIdx.x;
    int ox = tid & 31, oyr = tid >> 5;
    if (tid < 32) sB[tid] = b[tid];

    int iy0 = oy0 - 1, ix0 = ox0 - 1;

    float pin[3], pw[2];
    {
        const float* src = &g_sa[(n * 32 + 0) * 4096];
#pragma unroll
        for (int j = 0; j < 3; j++) {
            int i = tid + j * 256; float v = 0.f;
            if (i < 612) {
                int iy = i / 34, ix = i % 34;
                int gy = iy0 + iy, gx = ix0 + ix;
                if ((unsigned)gy < 64u && (unsigned)gx < 64u) v = src[gy * 64 + gx];
            }
            pin[j] = v;
        }
#pragma unroll
        for (int j = 0; j < 2; j++) {
            int i = tid + j * 256; float v = 0.f;
            if (i < 288) { int o = i & 31, tap = i >> 5; v = w[(o * 32 + 0) * 9 + tap]; }
            pw[j] = v;
        }
    }
#pragma unroll
    for (int j = 0; j < 3; j++) { int i = tid + j * 256; if (i < 612) sIn[0][i] = pin[j]; }
#pragma unroll
    for (int j = 0; j < 2; j++) { int i = tid + j * 256; if (i < 288) sW[0][i] = pw[j]; }
    __syncthreads();

    unsigned long long accA[16], accB[16];
    const unsigned long long* sB2 = (const unsigned long long*)sB;
#pragma unroll
    for (int o = 0; o < 16; o++) { accA[o] = sB2[o]; accB[o] = sB2[o]; }

    for (int ic = 0; ic < 32; ic++) {
        int cur = ic & 1;
        if (ic < 31) {
            const float* src = &g_sa[(n * 32 + ic + 1) * 4096];
#pragma unroll
            for (int j = 0; j < 3; j++) {
                int i = tid + j * 256; float v = 0.f;
                if (i < 612) {
                    int iy = i / 34, ix = i % 34;
                    int gy = iy0 + iy, gx = ix0 + ix;
                    if ((unsigned)gy < 64u && (unsigned)gx < 64u) v = src[gy * 64 + gx];
                }
                pin[j] = v;
            }
#pragma unroll
            for (int j = 0; j < 2; j++) {
                int i = tid + j * 256; float v = 0.f;
                if (i < 288) { int o = i & 31, tap = i >> 5; v = w[(o * 32 + ic + 1) * 9 + tap]; }
                pw[j] = v;
            }
        }
#pragma unroll
        for (int kh = 0; kh < 3; kh++) {
            const float* rA = &sIn[cur][(oyr + kh) * 34 + ox];
            const float* rB = rA + 8 * 34;
#pragma unroll
            for (int kw = 0; kw < 3; kw++) {
                unsigned long long vA2 = pack_dup(rA[kw]);
                unsigned long long vB2 = pack_dup(rB[kw]);
                const ulonglong2* wq = (const ulonglong2*)&sW[cur][(kh * 3 + kw) * 32];
#pragma unroll
                for (int o2 = 0; o2 < 8; o2++) {
                    ulonglong2 ww = wq[o2];
                    FMA2(accA[2 * o2], vA2, ww.x);
                    FMA2(accA[2 * o2 + 1], vA2, ww.y);
                    FMA2(accB[2 * o2], vB2, ww.x);
                    FMA2(accB[2 * o2 + 1], vB2, ww.y);
                }
            }
        }
        if (ic < 31) {
#pragma unroll
            for (int j = 0; j < 3; j++) { int i = tid + j * 256; if (i < 612) sIn[1 - cur][i] = pin[j]; }
#pragma unroll
            for (int j = 0; j < 2; j++) { int i = tid + j * 256; if (i < 288) sW[1 - cur][i] = pw[j]; }
        }
        __syncthreads();
    }

    int gyA = oy0 + oyr, gyB = gyA + 8, gx = ox0 + ox;
#pragma unroll
    for (int o = 0; o < 16; o++) {
        unsigned lo, hi;
        UNPACK2(lo, hi, accA[o]);
        g_f[((n * 32 + 2 * o) * 64 + gyA) * 64 + gx] = fmaxf(__uint_as_float(lo), 0.f);
        g_f[((n * 32 + 2 * o + 1) * 64 + gyA) * 64 + gx] = fmaxf(__uint_as_float(hi), 0.f);
        UNPACK2(lo, hi, accB[o]);
        g_f[((n * 32 + 2 * o) * 64 + gyB) * 64 + gx] = fmaxf(__uint_as_float(lo), 0.f);
        g_f[((n * 32 + 2 * o + 1) * 64 + gyB) * 64 + gx] = fmaxf(__uint_as_float(hi), 0.f);
    }
}

// =================== mp2: 32->2, k3, p1 (2 px/thread) ===================
__global__ void __launch_bounds__(256, 2)
mp2_kernel(const float* __restrict__ w, const float* __restrict__ b,
           float* __restrict__ out) {
    __shared__ __align__(8) float sIn[2][18 * 34];
    __shared__ __align__(8) float sW[2][18];
    int n = blockIdx.z;
    int ox0 = blockIdx.x * 32, oy0 = blockIdx.y * 16;
    int tid = threadIdx.x;
    int ox = tid & 31, oyr = tid >> 5;

    int iy0 = oy0 - 1, ix0 = ox0 - 1;

    float pin[3], pwv;
    {
        const float* src = &g_f[(n * 32 + 0) * 4096];
#pragma unroll
        for (int j = 0; j < 3; j++) {
            int i = tid + j * 256; float v = 0.f;
            if (i < 612) {
                int iy = i / 34, ix = i % 34;
                int gy = iy0 + iy, gx = ix0 + ix;
                if ((unsigned)gy < 64u && (unsigned)gx < 64u) v = src[gy * 64 + gx];
            }
            pin[j] = v;
        }
        pwv = (tid < 18) ? w[((tid & 1) * 32 + 0) * 9 + (tid >> 1)] : 0.f;
    }
#pragma unroll
    for (int j = 0; j < 3; j++) { int i = tid + j * 256; if (i < 612) sIn[0][i] = pin[j]; }
    if (tid < 18) sW[0][tid] = pwv;
    __syncthreads();

    unsigned long long accA2, accB2;
    PACK2(accA2, __float_as_uint(b[0]), __float_as_uint(b[1]));
    accB2 = accA2;

    for (int ic = 0; ic < 32; ic++) {
        int cur = ic & 1;
        if (ic < 31) {
            const float* src = &g_f[(n * 32 + ic + 1) * 4096];
#pragma unroll
            for (int j = 0; j < 3; j++) {
                int i = tid + j * 256; float v = 0.f;
                if (i < 612) {
                    int iy = i / 34, ix = i % 34;
                    int gy = iy0 + iy, gx = ix0 + ix;
                    if ((unsigned)gy < 64u && (unsigned)gx < 64u) v = src[gy * 64 + gx];
                }
                pin[j] = v;
            }
            pwv = (tid < 18) ? w[((tid & 1) * 32 + ic + 1) * 9 + (tid >> 1)] : 0.f;
        }
        const unsigned long long* wp2 = (const unsigned long long*)&sW[cur][0];
#pragma unroll
        for (int kh = 0; kh < 3; kh++) {
            const float* rA = &sIn[cur][(oyr + kh) * 34 + ox];
            const float* rB = rA + 8 * 34;
#pragma unroll
            for (int kw = 0; kw < 3; kw++) {
                unsigned long long w2 = wp2[kh * 3 + kw];
                FMA2(accA2, pack_dup(rA[kw]), w2);
                FMA2(accB2, pack_dup(rB[kw]), w2);
            }
        }
        if (ic < 31) {
#pragma unroll
            for (int j = 0; j < 3; j++) { int i = tid + j * 256; if (i < 612) sIn[1 - cur][i] = pin[j]; }
            if (tid < 18) sW[1 - cur][tid] = pwv;
        }
        __syncthreads();
    }
    int gyA = oy0 + oyr, gyB = gyA + 8, gx = ox0 + ox;
    unsigned lo, hi;
    UNPACK2(lo, hi, accA2);
    out[((n * 2 + 0) * 64 + gyA) * 64 + gx] = __uint_as_float(lo);
    out[((n * 2 + 1) * 64 + gyA) * 64 + gx] = __uint_as_float(hi);
    UNPACK2(lo, hi, accB2);
    out[((n * 2 + 0) * 64 + gyB) * 64 + gx] = __uint_as_float(lo);
    out[((n * 2 + 1) * 64 + gyB) * 64 + gx] = __uint_as_float(hi);
}

// =================== launch ===================
extern "C" void kernel_launch(void* const* d_in, const int* in_sizes, int n_in,
                              void* d_out, int out_size) {
    const float* images = (const float*)d_in[0];
    const float* actions = (const float*)d_in[1];
    const float* pe_w1 = (const float*)d_in[2];
    const float* pe_b1 = (const float*)d_in[3];
    const float* pe_w2 = (const float*)d_in[4];
    const float* pe_b2 = (const float*)d_in[5];
    const float* ae_w1 = (const float*)d_in[6];
    const float* ae_b1 = (const float*)d_in[7];
    const float* ae_w2 = (const float*)d_in[8];
    const float* ae_b2 = (const float*)d_in[9];
    const float* mp_w1 = (const float*)d_in[10];
    const float* mp_b1 = (const float*)d_in[11];
    const float* mp_w2 = (const float*)d_in[12];
    const float* mp_b2 = (const float*)d_in[13];
    float* out = (float*)d_out;

    cudaFuncSetAttribute(conv2_mma_kernel,
                         cudaFuncAttributeMaxDynamicSharedMemorySize, C2_SMEM);

    uint32_t* wtu;  cudaGetSymbolAddress((void**)&wtu, g_wtu);
    uint32_t* h1hi; cudaGetSymbolAddress((void**)&h1hi, g_h1hi);
    uint32_t* h1lo; cudaGetSymbolAddress((void**)&h1lo, g_h1lo);
    float* h2p;     cudaGetSymbolAddress((void**)&h2p, g_h2);

    ae_kernel<<<NB, 256>>>(actions, ae_w1, ae_b1, ae_w2, ae_b2);
    wsplit_kernel<<<50, 256>>>(pe_w2);
    conv1_kernel<<<dim3(4, 8, NB), 256>>>(images, pe_w1, pe_b1);
    conv2_mma_kernel<<<dim3(32, NB), 256, C2_SMEM>>>(h1hi, h1lo, wtu, pe_b2, h2p);
    xconv_kernel<<<dim3(32, NB), 256>>>();
    mp1_kernel<<<dim3(2, 4, NB), 256>>>(mp_w1, mp_b1);
    mp2_kernel<<<dim3(2, 4, NB), 256>>>(mp_w2, mp_b2, out);
}

// round 9
// speedup vs baseline: 1.3364x; 1.3364x over previous
#include <cuda_runtime.h>
#include <cuda_bf16.h>
#include <cstdint>

#define NB 64
#define CC 32
#define KK 5
#define ADIM 4
#define AHID 256

// packed f32x2 helpers
#define PACK2(out, lo, hi) \
    asm("mov.b64 %0, {%1, %2};" : "=l"(out) : "r"(lo), "r"(hi))
#define FMA2(acc, a, b) \
    asm("fma.rn.f32x2 %0, %1, %2, %0;" : "+l"(acc) : "l"(a), "l"(b))
#define UNPACK2(lo, hi, in) \
    asm("mov.b64 {%0, %1}, %2;" : "=r"(lo), "=r"(hi) : "l"(in))

__device__ __forceinline__ unsigned long long pack_dup(float v) {
    unsigned long long r; unsigned u = __float_as_uint(v);
    PACK2(r, u, u); return r;
}

// ---------------- scratch ----------------
__device__ float g_h1[NB * CC * 128 * 128];
__device__ float g_h2[NB * CC * 64 * 64];
__device__ float g_ker[NB * CC * KK * KK];
__device__ float g_sa[NB * CC * 64 * 64];
__device__ float g_f [NB * CC * 64 * 64];

// =================== action encoder MLP ===================
__global__ void ae_kernel(const float* __restrict__ act,
                          const float* __restrict__ w1, const float* __restrict__ b1,
                          const float* __restrict__ w2, const float* __restrict__ b2) {
    __shared__ float sH[AHID];
    __shared__ float sA[ADIM];
    int n = blockIdx.x, tid = threadIdx.x;
    if (tid < ADIM) sA[tid] = act[n * ADIM + tid];
    __syncthreads();
    float h = b1[tid];
#pragma unroll
    for (int i = 0; i < ADIM; i++) h = fmaf(sA[i], w1[i * AHID + tid], h);
    sH[tid] = fmaxf(h, 0.f);
    __syncthreads();
    for (int o = tid; o < CC * KK * KK; o += 256) {
        float acc = b2[o];
#pragma unroll 8
        for (int j = 0; j < AHID; j++) acc = fmaf(sH[j], w2[j * (CC * KK * KK) + o], acc);
        g_ker[n * (CC * KK * KK) + o] = acc;
    }
}

// =================== conv1: 3->32, k5, s2, p2, NHWC in ===================
// oc-split: each block computes 16 of 32 output channels (och = blockIdx.x&1)
__global__ void __launch_bounds__(256, 3)
conv1_kernel(const float* __restrict__ img,
             const float* __restrict__ w, const float* __restrict__ b) {
    __shared__ __align__(16) float sIn[2][3 * 35 * 34];
    __shared__ __align__(16) float sW[75 * 16];
    __shared__ __align__(8) float sB[16];
    int n = blockIdx.z;
    int och = blockIdx.x & 1;
    int ox0 = (blockIdx.x >> 1) * 32, oy0 = blockIdx.y * 16;
    int tid = threadIdx.x;

    for (int i = tid; i < 75 * 16; i += 256) {
        int o = i & 15, tap = i >> 4;
        int c = tap / 25, r = tap % 25, kh = r / 5, kw = r % 5;
        sW[i] = w[(((och * 16 + o) * 3 + c) * 5 + kh) * 5 + kw];
    }
    if (tid < 16) sB[tid] = b[och * 16 + tid];

    int iy0 = oy0 * 2 - 2, ix0 = ox0 * 2 - 2;
    for (int i = tid; i < 3 * 35 * 67; i += 256) {
        int c = i / (35 * 67), r = i % (35 * 67);
        int iy = r / 67, ix = r % 67;
        int gy = iy0 + iy, gx = ix0 + ix;
        float v = 0.f;
        if ((unsigned)gy < 256u && (unsigned)gx < 256u)
            v = img[((n * 256 + gy) * 256 + gx) * 3 + c];
        sIn[ix & 1][c * 1190 + iy * 34 + (ix >> 1)] = v;
    }
    __syncthreads();

    int ox = tid & 31, oyr = tid >> 5;
    unsigned long long accA[8], accB[8];
    const unsigned long long* sB2 = (const unsigned long long*)sB;
#pragma unroll
    for (int o = 0; o < 8; o++) { accA[o] = sB2[o]; accB[o] = sB2[o]; }

    for (int c = 0; c < 3; c++)
        for (int kh = 0; kh < 5; kh++) {
            int base = c * 1190 + (2 * oyr + kh) * 34 + ox;
            const float* pl[2] = { &sIn[0][base], &sIn[1][base] };
#pragma unroll
            for (int kw = 0; kw < 5; kw++) {
                float fA = pl[kw & 1][kw >> 1];
                float fB = pl[kw & 1][(kw >> 1) + 544];
                unsigned long long vA2 = pack_dup(fA);
                unsigned long long vB2 = pack_dup(fB);
                const ulonglong2* wq =
                    (const ulonglong2*)&sW[((c * 5 + kh) * 5 + kw) * 16];
#pragma unroll
                for (int o2 = 0; o2 < 4; o2++) {
                    ulonglong2 ww = wq[o2];
                    FMA2(accA[2 * o2], vA2, ww.x);
                    FMA2(accA[2 * o2 + 1], vA2, ww.y);
                    FMA2(accB[2 * o2], vB2, ww.x);
                    FMA2(accB[2 * o2 + 1], vB2, ww.y);
                }
            }
        }

    int gyA = oy0 + oyr, gyB = gyA + 8, gx = ox0 + ox;
#pragma unroll
    for (int o = 0; o < 8; o++) {
        int oc = och * 16 + 2 * o;
        unsigned lo, hi;
        UNPACK2(lo, hi, accA[o]);
        g_h1[((n * 32 + oc) * 128 + gyA) * 128 + gx] = fmaxf(__uint_as_float(lo), 0.f);
        g_h1[((n * 32 + oc + 1) * 128 + gyA) * 128 + gx] = fmaxf(__uint_as_float(hi), 0.f);
        UNPACK2(lo, hi, accB[o]);
        g_h1[((n * 32 + oc) * 128 + gyB) * 128 + gx] = fmaxf(__uint_as_float(lo), 0.f);
        g_h1[((n * 32 + oc + 1) * 128 + gyB) * 128 + gx] = fmaxf(__uint_as_float(hi), 0.f);
    }
}

// =================== conv2: 32->32, k5, s2, p2 (oc-split, occ 3) ===================
__global__ void __launch_bounds__(256, 3)
conv2_kernel(const float* __restrict__ w, const float* __restrict__ b) {
    __shared__ __align__(16) float sIn[2][2][1190];   // [buf][parity][35 x 34]
    __shared__ __align__(16) float sW[2][400];        // [buf][tap*16+o]
    __shared__ __align__(8) float sB[16];
    int n = blockIdx.z;
    int och = blockIdx.x & 1;
    int ox0 = (blockIdx.x >> 1) * 32, oy0 = blockIdx.y * 16;
    int tid = threadIdx.x;
    int ox = tid & 31, oyr = tid >> 5;
    if (tid < 16) sB[tid] = b[och * 16 + tid];

    int iy0 = oy0 * 2 - 2, ix0 = ox0 * 2 - 2;

    float pin[10], pw[2];
    {
        const float* src = &g_h1[(n * 32 + 0) * 16384];
#pragma unroll
        for (int j = 0; j < 10; j++) {
            int i = tid + j * 256; float v = 0.f;
            if (i < 2345) {
                int iy = i / 67, ix = i % 67;
                int gy = iy0 + iy, gx = ix0 + ix;
                if ((unsigned)gy < 128u && (unsigned)gx < 128u) v = src[gy * 128 + gx];
            }
            pin[j] = v;
        }
#pragma unroll
        for (int j = 0; j < 2; j++) {
            int i = tid + j * 256; float v = 0.f;
            if (i < 400) {
                int o = i & 15, tap = i >> 4;
                v = w[((och * 16 + o) * 32 + 0) * 25 + tap];
            }
            pw[j] = v;
        }
    }
#pragma unroll
    for (int j = 0; j < 10; j++) {
        int i = tid + j * 256;
        if (i < 2345) {
            int iy = i / 67, ix = i % 67;
            sIn[0][ix & 1][iy * 34 + (ix >> 1)] = pin[j];
        }
    }
#pragma unroll
    for (int j = 0; j < 2; j++) { int i = tid + j * 256; if (i < 400) sW[0][i] = pw[j]; }
    __syncthreads();

    unsigned long long accA[8], accB[8];
    const unsigned long long* sB2 = (const unsigned long long*)sB;
#pragma unroll
    for (int o = 0; o < 8; o++) { accA[o] = sB2[o]; accB[o] = sB2[o]; }

    for (int ic = 0; ic < 32; ic++) {
        int cur = ic & 1;
        if (ic < 31) {
            const float* src = &g_h1[(n * 32 + ic + 1) * 16384];
#pragma unroll
            for (int j = 0; j < 10; j++) {
                int i = tid + j * 256; float v = 0.f;
                if (i < 2345) {
                    int iy = i / 67, ix = i % 67;
                    int gy = iy0 + iy, gx = ix0 + ix;
                    if ((unsigned)gy < 128u && (unsigned)gx < 128u) v = src[gy * 128 + gx];
                }
                pin[j] = v;
            }
#pragma unroll
            for (int j = 0; j < 2; j++) {
                int i = tid + j * 256; float v = 0.f;
                if (i < 400) {
                    int o = i & 15, tap = i >> 4;
                    v = w[((och * 16 + o) * 32 + ic + 1) * 25 + tap];
                }
                pw[j] = v;
            }
        }
#pragma unroll
        for (int kh = 0; kh < 5; kh++) {
            int base = (2 * oyr + kh) * 34 + ox;
            const float* pl[2] = { &sIn[cur][0][base], &sIn[cur][1][base] };
#pragma unroll
            for (int kw = 0; kw < 5; kw++) {
                float fA = pl[kw & 1][kw >> 1];
                float fB = pl[kw & 1][(kw >> 1) + 544];
                unsigned long long vA2 = pack_dup(fA);
                unsigned long long vB2 = pack_dup(fB);
                const ulonglong2* wq = (const ulonglong2*)&sW[cur][(kh * 5 + kw) * 16];
#pragma unroll
                for (int o2 = 0; o2 < 4; o2++) {
                    ulonglong2 ww = wq[o2];
                    FMA2(accA[2 * o2], vA2, ww.x);
                    FMA2(accA[2 * o2 + 1], vA2, ww.y);
                    FMA2(accB[2 * o2], vB2, ww.x);
                    FMA2(accB[2 * o2 + 1], vB2, ww.y);
                }
            }
        }
        if (ic < 31) {
#pragma unroll
            for (int j = 0; j < 10; j++) {
                int i = tid + j * 256;
                if (i < 2345) {
                    int iy = i / 67, ix = i % 67;
                    sIn[1 - cur][ix & 1][iy * 34 + (ix >> 1)] = pin[j];
                }
            }
#pragma unroll
            for (int j = 0; j < 2; j++) { int i = tid + j * 256; if (i < 400) sW[1 - cur][i] = pw[j]; }
        }
        __syncthreads();
    }

    int gyA = oy0 + oyr, gyB = gyA + 8, gx = ox0 + ox;
#pragma unroll
    for (int o = 0; o < 8; o++) {
        int oc = och * 16 + 2 * o;
        unsigned lo, hi;
        UNPACK2(lo, hi, accA[o]);
        g_h2[((n * 32 + oc) * 64 + gyA) * 64 + gx] = fmaxf(__uint_as_float(lo), 0.f);
        g_h2[((n * 32 + oc + 1) * 64 + gyA) * 64 + gx] = fmaxf(__uint_as_float(hi), 0.f);
        UNPACK2(lo, hi, accB[o]);
        g_h2[((n * 32 + oc) * 64 + gyB) * 64 + gx] = fmaxf(__uint_as_float(lo), 0.f);
        g_h2[((n * 32 + oc + 1) * 64 + gyB) * 64 + gx] = fmaxf(__uint_as_float(hi), 0.f);
    }
}

// =================== cross-conv: depthwise k5 p2, register row-reuse ===================
__global__ void __launch_bounds__(256)
xconv_kernel() {
    __shared__ float sIn[68 * 68];
    __shared__ float sK[25];
    int c = blockIdx.x, n = blockIdx.y;
    int tid = threadIdx.x;
    const float* src = &g_h2[(n * 32 + c) * 4096];
    for (int i = tid; i < 68 * 68; i += 256) {
        int iy = i / 68, ix = i % 68;
        int gy = iy - 2, gx = ix - 2;
        sIn[i] = ((unsigned)gy < 64u && (unsigned)gx < 64u) ? src[gy * 64 + gx] : 0.f;
    }
    if (tid < 25) sK[tid] = g_ker[(n * 32 + c) * 25 + tid];
    __syncthreads();
    float k[25];
#pragma unroll
    for (int t = 0; t < 25; t++) k[t] = sK[t];

    int tx = tid & 63, ty = tid >> 6;
    int ybase = ty * 16;
    float acc[16];
#pragma unroll
    for (int j = 0; j < 16; j++) acc[j] = 0.f;

#pragma unroll
    for (int iy = 0; iy < 20; iy++) {
        const float* row = &sIn[(ybase + iy) * 68 + tx];
        float v0 = row[0], v1 = row[1], v2 = row[2], v3 = row[3], v4 = row[4];
#pragma unroll
        for (int kh = 0; kh < 5; kh++) {
            int j = iy - kh;
            if (j >= 0 && j < 16) {
                float a = acc[j];
                a = fmaf(v0, k[kh * 5 + 0], a);
                a = fmaf(v1, k[kh * 5 + 1], a);
                a = fmaf(v2, k[kh * 5 + 2], a);
                a = fmaf(v3, k[kh * 5 + 3], a);
                a = fmaf(v4, k[kh * 5 + 4], a);
                acc[j] = a;
            }
        }
    }
    float* dst = &g_sa[(n * 32 + c) * 4096 + tx];
#pragma unroll
    for (int j = 0; j < 16; j++) dst[(ybase + j) * 64] = acc[j];
}

// =================== mp1: 32->32, k3, p1, relu (oc-split, occ 3) ===================
__global__ void __launch_bounds__(256, 3)
mp1_kernel(const float* __restrict__ w, const float* __restrict__ b) {
    __shared__ __align__(16) float sIn[2][18 * 34];
    __shared__ __align__(16) float sW[2][144];
    __shared__ __align__(8) float sB[16];
    int n = blockIdx.z;
    int och = blockIdx.x & 1;
    int ox0 = (blockIdx.x >> 1) * 32, oy0 = blockIdx.y * 16;
    int tid = threadIdx.x;
    int ox = tid & 31, oyr = tid >> 5;
    if (tid < 16) sB[tid] = b[och * 16 + tid];

    int iy0 = oy0 - 1, ix0 = ox0 - 1;

    float pin[3], pwv;
    {
        const float* src = &g_sa[(n * 32 + 0) * 4096];
#pragma unroll
        for (int j = 0; j < 3; j++) {
            int i = tid + j * 256; float v = 0.f;
            if (i < 612) {
                int iy = i / 34, ix = i % 34;
                int gy = iy0 + iy, gx = ix0 + ix;
                if ((unsigned)gy < 64u && (unsigned)gx < 64u) v = src[gy * 64 + gx];
            }
            pin[j] = v;
        }
        pwv = 0.f;
        if (tid < 144) {
            int o = tid & 15, tap = tid >> 4;
            pwv = w[((och * 16 + o) * 32 + 0) * 9 + tap];
        }
    }
#pragma unroll
    for (int j = 0; j < 3; j++) { int i = tid + j * 256; if (i < 612) sIn[0][i] = pin[j]; }
    if (tid < 144) sW[0][tid] = pwv;
    __syncthreads();

    unsigned long long accA[8], accB[8];
    const unsigned long long* sB2 = (const unsigned long long*)sB;
#pragma unroll
    for (int o = 0; o < 8; o++) { accA[o] = sB2[o]; accB[o] = sB2[o]; }

    for (int ic = 0; ic < 32; ic++) {
        int cur = ic & 1;
        if (ic < 31) {
            const float* src = &g_sa[(n * 32 + ic + 1) * 4096];
#pragma unroll
            for (int j = 0; j < 3; j++) {
                int i = tid + j * 256; float v = 0.f;
                if (i < 612) {
                    int iy = i / 34, ix = i % 34;
                    int gy = iy0 + iy, gx = ix0 + ix;
                    if ((unsigned)gy < 64u && (unsigned)gx < 64u) v = src[gy * 64 + gx];
                }
                pin[j] = v;
            }
            pwv = 0.f;
            if (tid < 144) {
                int o = tid & 15, tap = tid >> 4;
                pwv = w[((och * 16 + o) * 32 + ic + 1) * 9 + tap];
            }
        }
#pragma unroll
        for (int kh = 0; kh < 3; kh++) {
            const float* rA = &sIn[cur][(oyr + kh) * 34 + ox];
            const float* rB = rA + 8 * 34;
#pragma unroll
            for (int kw = 0; kw < 3; kw++) {
                unsigned long long vA2 = pack_dup(rA[kw]);
                unsigned long long vB2 = pack_dup(rB[kw]);
                const ulonglong2* wq = (const ulonglong2*)&sW[cur][(kh * 3 + kw) * 16];
#pragma unroll
                for (int o2 = 0; o2 < 4; o2++) {
                    ulonglong2 ww = wq[o2];
                    FMA2(accA[2 * o2], vA2, ww.x);
                    FMA2(accA[2 * o2 + 1], vA2, ww.y);
                    FMA2(accB[2 * o2], vB2, ww.x);
                    FMA2(accB[2 * o2 + 1], vB2, ww.y);
                }
            }
        }
        if (ic < 31) {
#pragma unroll
            for (int j = 0; j < 3; j++) { int i = tid + j * 256; if (i < 612) sIn[1 - cur][i] = pin[j]; }
            if (tid < 144) sW[1 - cur][tid] = pwv;
        }
        __syncthreads();
    }

    int gyA = oy0 + oyr, gyB = gyA + 8, gx = ox0 + ox;
#pragma unroll
    for (int o = 0; o < 8; o++) {
        int oc = och * 16 + 2 * o;
        unsigned lo, hi;
        UNPACK2(lo, hi, accA[o]);
        g_f[((n * 32 + oc) * 64 + gyA) * 64 + gx] = fmaxf(__uint_as_float(lo), 0.f);
        g_f[((n * 32 + oc + 1) * 64 + gyA) * 64 + gx] = fmaxf(__uint_as_float(hi), 0.f);
        UNPACK2(lo, hi, accB[o]);
        g_f[((n * 32 + oc) * 64 + gyB) * 64 + gx] = fmaxf(__uint_as_float(lo), 0.f);
        g_f[((n * 32 + oc + 1) * 64 + gyB) * 64 + gx] = fmaxf(__uint_as_float(hi), 0.f);
    }
}

// =================== mp2: 32->2, k3, p1 (2 px/thread) ===================
__global__ void __launch_bounds__(256, 2)
mp2_kernel(const float* __restrict__ w, const float* __restrict__ b,
           float* __restrict__ out) {
    __shared__ __align__(8) float sIn[2][18 * 34];
    __shared__ __align__(8) float sW[2][18];
    int n = blockIdx.z;
    int ox0 = blockIdx.x * 32, oy0 = blockIdx.y * 16;
    int tid = threadIdx.x;
    int ox = tid & 31, oyr = tid >> 5;

    int iy0 = oy0 - 1, ix0 = ox0 - 1;

    float pin[3], pwv;
    {
        const float* src = &g_f[(n * 32 + 0) * 4096];
#pragma unroll
        for (int j = 0; j < 3; j++) {
            int i = tid + j * 256; float v = 0.f;
            if (i < 612) {
                int iy = i / 34, ix = i % 34;
                int gy = iy0 + iy, gx = ix0 + ix;
                if ((unsigned)gy < 64u && (unsigned)gx < 64u) v = src[gy * 64 + gx];
            }
            pin[j] = v;
        }
        pwv = (tid < 18) ? w[((tid & 1) * 32 + 0) * 9 + (tid >> 1)] : 0.f;
    }
#pragma unroll
    for (int j = 0; j < 3; j++) { int i = tid + j * 256; if (i < 612) sIn[0][i] = pin[j]; }
    if (tid < 18) sW[0][tid] = pwv;
    __syncthreads();

    unsigned long long accA2, accB2;
    PACK2(accA2, __float_as_uint(b[0]), __float_as_uint(b[1]));
    accB2 = accA2;

    for (int ic = 0; ic < 32; ic++) {
        int cur = ic & 1;
        if (ic < 31) {
            const float* src = &g_f[(n * 32 + ic + 1) * 4096];
#pragma unroll
            for (int j = 0; j < 3; j++) {
                int i = tid + j * 256; float v = 0.f;
                if (i < 612) {
                    int iy = i / 34, ix = i % 34;
                    int gy = iy0 + iy, gx = ix0 + ix;
                    if ((unsigned)gy < 64u && (unsigned)gx < 64u) v = src[gy * 64 + gx];
                }
                pin[j] = v;
            }
            pwv = (tid < 18) ? w[((tid & 1) * 32 + ic + 1) * 9 + (tid >> 1)] : 0.f;
        }
        const unsigned long long* wp2 = (const unsigned long long*)&sW[cur][0];
#pragma unroll
        for (int kh = 0; kh < 3; kh++) {
            const float* rA = &sIn[cur][(oyr + kh) * 34 + ox];
            const float* rB = rA + 8 * 34;
#pragma unroll
            for (int kw = 0; kw < 3; kw++) {
                unsigned long long w2 = wp2[kh * 3 + kw];
                FMA2(accA2, pack_dup(rA[kw]), w2);
                FMA2(accB2, pack_dup(rB[kw]), w2);
            }
        }
        if (ic < 31) {
#pragma unroll
            for (int j = 0; j < 3; j++) { int i = tid + j * 256; if (i < 612) sIn[1 - cur][i] = pin[j]; }
            if (tid < 18) sW[1 - cur][tid] = pwv;
        }
        __syncthreads();
    }
    int gyA = oy0 + oyr, gyB = gyA + 8, gx = ox0 + ox;
    unsigned lo, hi;
    UNPACK2(lo, hi, accA2);
    out[((n * 2 + 0) * 64 + gyA) * 64 + gx] = __uint_as_float(lo);
    out[((n * 2 + 1) * 64 + gyA) * 64 + gx] = __uint_as_float(hi);
    UNPACK2(lo, hi, accB2);
    out[((n * 2 + 0) * 64 + gyB) * 64 + gx] = __uint_as_float(lo);
    out[((n * 2 + 1) * 64 + gyB) * 64 + gx] = __uint_as_float(hi);
}

// =================== launch ===================
extern "C" void kernel_launch(void* const* d_in, const int* in_sizes, int n_in,
                              void* d_out, int out_size) {
    const float* images = (const float*)d_in[0];
    const float* actions = (const float*)d_in[1];
    const float* pe_w1 = (const float*)d_in[2];
    const float* pe_b1 = (const float*)d_in[3];
    const float* pe_w2 = (const float*)d_in[4];
    const float* pe_b2 = (const float*)d_in[5];
    const float* ae_w1 = (const float*)d_in[6];
    const float* ae_b1 = (const float*)d_in[7];
    const float* ae_w2 = (const float*)d_in[8];
    const float* ae_b2 = (const float*)d_in[9];
    const float* mp_w1 = (const float*)d_in[10];
    const float* mp_b1 = (const float*)d_in[11];
    const float* mp_w2 = (const float*)d_in[12];
    const float* mp_b2 = (const float*)d_in[13];
    float* out = (float*)d_out;

    ae_kernel<<<NB, 256>>>(actions, ae_w1, ae_b1, ae_w2, ae_b2);
    conv1_kernel<<<dim3(8, 8, NB), 256>>>(images, pe_w1, pe_b1);
    conv2_kernel<<<dim3(4, 4, NB), 256>>>(pe_w2, pe_b2);
    xconv_kernel<<<dim3(32, NB), 256>>>();
    mp1_kernel<<<dim3(4, 4, NB), 256>>>(mp_w1, mp_b1);
    mp2_kernel<<<dim3(2, 4, NB), 256>>>(mp_w2, mp_b2, out);
}